// round 1
// baseline (speedup 1.0000x reference)
#include <cuda_runtime.h>

// Problem constants
#define N_PTS 16384
#define DIM   512
#define OUT_D 512
#define KNN   10

// Tiling
#define BM   128
#define BN   128
#define KCH  32
#define TPB  256
#define LDS_ 132   // smem row stride (floats), 16B-aligned

#define INF_F __int_as_float(0x7f800000)

// Scratch (static device globals: allocation-free per harness rules)
__device__ float g_sq[N_PTS];
__device__ float g_xW[N_PTS * OUT_D];

// ---------------- packed f32x2 helpers ----------------
__device__ __forceinline__ unsigned long long pack2(float x, float y) {
    unsigned long long r;
    asm("mov.b64 %0, {%1, %2};" : "=l"(r) : "f"(x), "f"(y));
    return r;
}
__device__ __forceinline__ void unpack2(unsigned long long v, float &a, float &b) {
    asm("mov.b64 {%0, %1}, %2;" : "=f"(a), "=f"(b) : "l"(v));
}
__device__ __forceinline__ void fma2(unsigned long long &d, unsigned long long a, unsigned long long b) {
    asm("fma.rn.f32x2 %0, %1, %2, %0;" : "+l"(d) : "l"(a), "l"(b));
}

// ---------------- shared tile loaders ----------------
// Transposed loader: dst[k][m], k in [0,KCH), m in [0,128). src row-major, ld = DIM.
__device__ __forceinline__ void load_T(float *dst, const float *__restrict__ src,
                                       int row0, int kc, int ld) {
    int t = threadIdx.x;
#pragma unroll
    for (int i = 0; i < 4; i++) {
        int idx = t + i * TPB;      // 0..1023 (128 rows x 8 float4)
        int r   = idx >> 3;
        int f4  = idx & 7;
        float4 v = *(const float4 *)(src + (long)(row0 + r) * ld + kc + f4 * 4);
        dst[(f4 * 4 + 0) * LDS_ + r] = v.x;
        dst[(f4 * 4 + 1) * LDS_ + r] = v.y;
        dst[(f4 * 4 + 2) * LDS_ + r] = v.z;
        dst[(f4 * 4 + 3) * LDS_ + r] = v.w;
    }
}
// Natural loader: dst[k][n] from src rows kc..kc+KCH, cols col0..col0+127.
__device__ __forceinline__ void load_N(float *dst, const float *__restrict__ src,
                                       int kc, int col0, int ld) {
    int t = threadIdx.x;
#pragma unroll
    for (int i = 0; i < 4; i++) {
        int idx = t + i * TPB;      // 1024 float4: 32 per row x 32 rows
        int kk  = idx >> 5;
        int c4  = idx & 31;
        float4 v = *(const float4 *)(src + (long)(kc + kk) * ld + col0 + c4 * 4);
        *(float4 *)(dst + kk * LDS_ + c4 * 4) = v;
    }
}

// Inner product mainloop step: acc[i][j2] += a[m_i] * {b[n_2j2], b[n_2j2+1]}
__device__ __forceinline__ void mma_chunk(const float *As, const float *Bs,
                                          int tx, int ty,
                                          unsigned long long acc[8][4]) {
#pragma unroll 8
    for (int kk = 0; kk < KCH; kk++) {
        const float *ar = As + kk * LDS_ + ty * 8;
        const float *br = Bs + kk * LDS_ + tx * 8;
        unsigned long long b2[4], a2[8];
#pragma unroll
        for (int j = 0; j < 4; j++)
            b2[j] = *(const unsigned long long *)(br + j * 2);
#pragma unroll
        for (int i = 0; i < 8; i++) {
            float av = ar[i];
            a2[i] = pack2(av, av);
        }
#pragma unroll
        for (int i = 0; i < 8; i++)
#pragma unroll
            for (int j = 0; j < 4; j++)
                fma2(acc[i][j], a2[i], b2[j]);
    }
}

// ---------------- top-k insert (register-resident, static indices) ----------------
__device__ __forceinline__ void topk_insert(float (&bd)[KNN], int (&bi)[KNN],
                                            float d, int idx) {
    bd[KNN - 1] = d;
    bi[KNN - 1] = idx;
#pragma unroll
    for (int p = KNN - 1; p > 0; p--) {
        if (bd[p] < bd[p - 1]) {
            float td = bd[p]; bd[p] = bd[p - 1]; bd[p - 1] = td;
            int   ti = bi[p]; bi[p] = bi[p - 1]; bi[p - 1] = ti;
        }
    }
}

// ---------------- kernel A: row squared norms ----------------
__global__ void sq_kernel(const float *__restrict__ x) {
    int row  = blockIdx.x * 8 + (threadIdx.x >> 5);
    int lane = threadIdx.x & 31;
    const float4 *xr = (const float4 *)(x + (long)row * DIM);
    float s = 0.f;
#pragma unroll
    for (int i = 0; i < 4; i++) {
        float4 v = xr[lane + i * 32];
        s += v.x * v.x + v.y * v.y + v.z * v.z + v.w * v.w;
    }
#pragma unroll
    for (int o = 16; o; o >>= 1) s += __shfl_xor_sync(0xFFFFFFFFu, s, o);
    if (lane == 0) g_sq[row] = s;
}

// ---------------- kernel B: xW = x @ A ----------------
__global__ void __launch_bounds__(TPB) xw_kernel(const float *__restrict__ x,
                                                 const float *__restrict__ A) {
    __shared__ float Xs[KCH * LDS_];
    __shared__ float Ws[KCH * LDS_];
    int m0 = blockIdx.x * BM;
    int n0 = blockIdx.y * BN;
    int w = threadIdx.x >> 5, l = threadIdx.x & 31;
    int tx = (l & 7) | ((w & 1) << 3);
    int ty = (l >> 3) | ((w >> 1) << 2);

    unsigned long long acc[8][4];
#pragma unroll
    for (int i = 0; i < 8; i++)
#pragma unroll
        for (int j = 0; j < 4; j++) acc[i][j] = 0ull;

    for (int kc = 0; kc < DIM; kc += KCH) {
        __syncthreads();
        load_T(Xs, x, m0, kc, DIM);
        load_N(Ws, A, kc, n0, OUT_D);
        __syncthreads();
        mma_chunk(Xs, Ws, tx, ty, acc);
    }
#pragma unroll
    for (int i = 0; i < 8; i++) {
        int m = m0 + ty * 8 + i;
#pragma unroll
        for (int j = 0; j < 4; j++) {
            float v0, v1;
            unpack2(acc[i][j], v0, v1);
            int n = n0 + tx * 8 + j * 2;
            g_xW[(long)m * OUT_D + n]     = v0;
            g_xW[(long)m * OUT_D + n + 1] = v1;
        }
    }
}

// ---------------- kernel C: fused distances + top-10 + gather-sum ----------------
__global__ void __launch_bounds__(TPB, 1) knn_kernel(const float *__restrict__ x,
                                                     float *__restrict__ out) {
    extern __shared__ float sm[];
    float *As = sm;
    float *Bs = As + KCH * LDS_;
    float *Ds = Bs + KCH * LDS_;          // BM x LDS_ distance tile
    __shared__ int fidx[BM][KNN];

    int r0  = blockIdx.x * BM;
    int tid = threadIdx.x;
    int w = tid >> 5, l = tid & 31;
    int tx = (l & 7) | ((w & 1) << 3);
    int ty = (l >> 3) | ((w >> 1) << 2);
    int rowOwn = tid & 127;
    int half   = tid >> 7;

    float bd[KNN];
    int   bi[KNN];
#pragma unroll
    for (int k = 0; k < KNN; k++) { bd[k] = INF_F; bi[k] = 0; }
    float th = INF_F;

    float sqi[8];
#pragma unroll
    for (int i = 0; i < 8; i++) sqi[i] = g_sq[r0 + ty * 8 + i];

    for (int j0 = 0; j0 < N_PTS; j0 += BN) {
        unsigned long long acc[8][4];
#pragma unroll
        for (int i = 0; i < 8; i++)
#pragma unroll
            for (int j = 0; j < 4; j++) acc[i][j] = 0ull;

        for (int kc = 0; kc < DIM; kc += KCH) {
            __syncthreads();                 // protects As/Bs (and Ds vs prev scan)
            load_T(As, x, r0, kc, DIM);
            load_T(Bs, x, j0, kc, DIM);
            __syncthreads();
            mma_chunk(As, Bs, tx, ty, acc);
        }

        // epilogue: d2 = |xi|^2 + |xj|^2 - 2*dot ; diagonal -> +inf
#pragma unroll
        for (int i = 0; i < 8; i++) {
            int gm = r0 + ty * 8 + i;
#pragma unroll
            for (int j = 0; j < 4; j++) {
                float v0, v1;
                unpack2(acc[i][j], v0, v1);
                int n  = tx * 8 + j * 2;
                int gn = j0 + n;
                float sj0 = g_sq[gn], sj1 = g_sq[gn + 1];
                float d0 = sqi[i] + sj0 - 2.0f * v0;
                float d1 = sqi[i] + sj1 - 2.0f * v1;
                if (gn == gm)     d0 = INF_F;
                if (gn + 1 == gm) d1 = INF_F;
                float2 dv; dv.x = d0; dv.y = d1;
                *(float2 *)(Ds + (ty * 8 + i) * LDS_ + n) = dv;
            }
        }
        __syncthreads();

        // scan: thread owns (rowOwn, half); 64 candidates per tile
        {
            const float *dr = Ds + rowOwn * LDS_ + half * 64;
            int jb = j0 + half * 64;
#pragma unroll 4
            for (int c4 = 0; c4 < 16; c4++) {
                float4 v = *(const float4 *)(dr + c4 * 4);
                int cb = jb + c4 * 4;
                if (v.x < th) { topk_insert(bd, bi, v.x, cb + 0); th = bd[KNN - 1]; }
                if (v.y < th) { topk_insert(bd, bi, v.y, cb + 1); th = bd[KNN - 1]; }
                if (v.z < th) { topk_insert(bd, bi, v.z, cb + 2); th = bd[KNN - 1]; }
                if (v.w < th) { topk_insert(bd, bi, v.w, cb + 3); th = bd[KNN - 1]; }
            }
        }
    }

    // merge the two per-row half-lists (both sorted ascending)
    __syncthreads();
    float *md = Ds;                      // 256*KNN floats
    int   *mi = (int *)(Ds + 4096);
#pragma unroll
    for (int k = 0; k < KNN; k++) {
        md[tid * KNN + k] = bd[k];
        mi[tid * KNN + k] = bi[k];
    }
    __syncthreads();
    if (tid < BM) {
        const float *da = md + tid * KNN;
        const int   *ia = mi + tid * KNN;
        const float *db = md + (tid + 128) * KNN;
        const int   *ib = mi + (tid + 128) * KNN;
        int pa = 0, pb = 0;
#pragma unroll
        for (int k = 0; k < KNN; k++) {
            float va = (pa < KNN) ? da[pa] : INF_F;
            float vb = (pb < KNN) ? db[pb] : INF_F;
            bool takeA = (va < vb) || (va == vb && ia[pa] < ib[pb]);
            if (takeA) { fidx[tid][k] = ia[pa]; pa++; }
            else       { fidx[tid][k] = ib[pb]; pb++; }
        }
    }
    __syncthreads();

    // gather-sum: out[row] = sum_k xW[fidx[row][k]]
    {
        int c  = tid & 127;   // float4 column
        int rh = tid >> 7;
        for (int pr = 0; pr < 64; pr++) {
            int row = pr * 2 + rh;
            float4 s = make_float4(0.f, 0.f, 0.f, 0.f);
#pragma unroll
            for (int k = 0; k < KNN; k++) {
                int j = fidx[row][k];
                float4 v = *(const float4 *)(g_xW + (long)j * OUT_D + c * 4);
                s.x += v.x; s.y += v.y; s.z += v.z; s.w += v.w;
            }
            *(float4 *)(out + (long)(r0 + row) * OUT_D + c * 4) = s;
        }
    }
}

// ---------------- launcher ----------------
extern "C" void kernel_launch(void *const *d_in, const int *in_sizes, int n_in,
                              void *d_out, int out_size) {
    const float *x = (const float *)d_in[0];
    const float *A = (const float *)d_in[1];
    float *out = (float *)d_out;

    static int configured = 0;
    size_t smem_c = (size_t)(2 * KCH + BM) * LDS_ * sizeof(float);  // 101,376 B
    if (!configured) {
        cudaFuncSetAttribute(knn_kernel, cudaFuncAttributeMaxDynamicSharedMemorySize,
                             (int)smem_c);
        configured = 1;
    }

    sq_kernel<<<N_PTS / 8, TPB>>>(x);
    xw_kernel<<<dim3(N_PTS / BM, OUT_D / BN), TPB>>>(x, A);
    knn_kernel<<<N_PTS / BM, TPB, smem_c>>>(x, out);
}